// round 4
// baseline (speedup 1.0000x reference)
#include <cuda_runtime.h>
#include <stdint.h>
#include <math.h>

// ---------------- problem constants ----------------
#define TT   64            // T
#define NB   256           // N
#define HD   1024          // H
#define ZDIM 1024          // ZS*ZC
#define AD   48            // AS*AC
#define G3   3072          // 3H
#define KAW  1072          // ZDIM + AD
#define TNP  (TT*NB)       // 16384
#define NZ   (NB*ZDIM)     // 262144
#define NH   (NB*HD)       // 262144

// output layout (floats): x_logits, r_loc, c_logits, z_prior_logits, z_post_logits
#define OFF_X     ((size_t)0)
#define OFF_R     ((size_t)TT*NB*ZDIM)          // 16777216
#define OFF_C     (OFF_R + (size_t)TT*NB)       // 16793600
#define OFF_PRIOR (OFF_C + (size_t)TT*NB)       // 16809984
#define OFF_POST  (OFF_PRIOR + (size_t)TT*NB*ZDIM) // 33587200

// ---------------- device scratch (static, no allocs) ----------------
__device__ float g_ee  [(size_t)TNP*ZDIM];  // e@enc_W[H:] + enc_b
__device__ float g_gum [(size_t)TNP*ZDIM];  // gumbel noise
__device__ float g_ai  [(size_t)TNP*G3];    // a@Wih_a^T + bih
__device__ float g_h   [(size_t)TNP*HD];    // all hidden states
__device__ float g_gh  [NB*G3];             // h@Whh^T + bhh (one step)
__device__ float g_WhhT[HD*G3];             // Whh^T  [k][g]
__device__ float g_WihT[KAW*G3];            // Wih^T  [k][g]
__device__ int   g_zidx[TT*NB*32];          // sampled categorical indices
__device__ unsigned g_keys[2*TT];           // per-timestep threefry keys

// ---------------- threefry2x32-20 (JAX-compatible) ----------------
__device__ __forceinline__ void tf2x32(unsigned k0, unsigned k1,
                                       unsigned x0, unsigned x1,
                                       unsigned &o0, unsigned &o1) {
    unsigned ks0 = k0, ks1 = k1, ks2 = k0 ^ k1 ^ 0x1BD11BDAu;
    x0 += ks0; x1 += ks1;
    const int RA[4] = {13, 15, 26, 6};
    const int RB[4] = {17, 29, 16, 24};
#pragma unroll
    for (int i = 0; i < 5; i++) {
#pragma unroll
        for (int j = 0; j < 4; j++) {
            int r = (i & 1) ? RB[j] : RA[j];
            x0 += x1;
            x1 = (x1 << r) | (x1 >> (32 - r));
            x1 ^= x0;
        }
        unsigned a = (i == 0) ? ks1 : (i == 1) ? ks2 : (i == 2) ? ks0 : (i == 3) ? ks1 : ks2;
        unsigned b = (i == 0) ? ks2 : (i == 1) ? ks0 : (i == 2) ? ks1 : (i == 3) ? ks2 : ks0;
        x0 += a; x1 += b + (unsigned)(i + 1);
    }
    o0 = x0; o1 = x1;
}

// keys[t] = threefry((0,42),(0,t))  (partitionable "foldlike" split)
__global__ void keys_k() {
    int t = threadIdx.x;
    if (t < TT) {
        unsigned o0, o1;
        tf2x32(0u, 42u, 0u, (unsigned)t, o0, o1);
        g_keys[2*t]   = o0;
        g_keys[2*t+1] = o1;
    }
}

// gumbel[t][i] from bits = o0^o1 of threefry(key_t, (0, i)); g = -log(-log(u))
__global__ void gumbel_k() {
    size_t L = (size_t)blockIdx.x * blockDim.x + threadIdx.x;
    if (L >= (size_t)TNP * ZDIM) return;
    int t = (int)(L >> 18);            // NZ = 2^18
    unsigned i = (unsigned)(L & 0x3FFFFu);
    unsigned o0, o1;
    tf2x32(g_keys[2*t], g_keys[2*t+1], 0u, i, o0, o1);
    unsigned bits = o0 ^ o1;
    float u = __uint_as_float((bits >> 9) | 0x3f800000u) - 1.0f;
    if (!(u > 0.0f)) u = 1.17549435e-38f;   // tiny clamp (matches jax uniform minval)
    float l1 = (float)log((double)u);        // round each log like XLA does
    float g  = -(float)log((double)(-l1));
    g_gum[L] = g;
}

// ---------------- transpose: out[c][r] = in[r][c], in is [R][C] ----------------
__global__ void transpose_k(const float* __restrict__ in, float* __restrict__ outp,
                            int R, int C) {
    __shared__ float tile[32][33];
    int c0 = blockIdx.x * 32, r0 = blockIdx.y * 32;
    int x = threadIdx.x, y = threadIdx.y;
#pragma unroll
    for (int dy = 0; dy < 32; dy += 8) {
        int r = r0 + y + dy, c = c0 + x;
        if (r < R && c < C) tile[y + dy][x] = in[(size_t)r * C + c];
    }
    __syncthreads();
#pragma unroll
    for (int dy = 0; dy < 32; dy += 8) {
        int orow = c0 + y + dy, ocol = r0 + x;
        if (orow < C && ocol < R) outp[(size_t)orow * R + ocol] = tile[x][y + dy];
    }
}

// ---------------- generic SGEMM: C = A[M,K] @ B[K,N] (+bias[col]) (+addsrc) ----
// exact-multiple tiling; M,N implied by grid (grid.x = N/BN, grid.y = M/BM)
template<int BM, int BN, int BK, int TM, int TNt>
__global__ void sgemm_k(const float* __restrict__ A, int lda,
                        const float* __restrict__ B, int ldb,
                        float* __restrict__ C, int ldc, int K,
                        const float* __restrict__ bias,
                        const float* __restrict__ addsrc, int ldadd) {
    constexpr int TH = (BM / TM) * (BN / TNt);
    __shared__ float As[BK][BM];
    __shared__ float Bs[BK][BN];
    int tid = threadIdx.x;
    int bm = blockIdx.y * BM, bn = blockIdx.x * BN;
    int tx = tid % (BN / TNt), ty = tid / (BN / TNt);
    float acc[TM][TNt];
#pragma unroll
    for (int i = 0; i < TM; i++)
#pragma unroll
        for (int j = 0; j < TNt; j++) acc[i][j] = 0.0f;

    for (int k0 = 0; k0 < K; k0 += BK) {
#pragma unroll
        for (int i = tid; i < BM * BK; i += TH) {
            int r = i / BK, c = i % BK;
            As[c][r] = A[(size_t)(bm + r) * lda + k0 + c];
        }
#pragma unroll
        for (int i = tid; i < BK * BN; i += TH) {
            int r = i / BN, c = i % BN;
            Bs[r][c] = B[(size_t)(k0 + r) * ldb + bn + c];
        }
        __syncthreads();
#pragma unroll
        for (int kk = 0; kk < BK; kk++) {
            float av[TM], bv[TNt];
#pragma unroll
            for (int i = 0; i < TM; i++) av[i] = As[kk][ty * TM + i];
#pragma unroll
            for (int j = 0; j < TNt; j++) bv[j] = Bs[kk][tx * TNt + j];
#pragma unroll
            for (int i = 0; i < TM; i++)
#pragma unroll
                for (int j = 0; j < TNt; j++)
                    acc[i][j] = fmaf(av[i], bv[j], acc[i][j]);
        }
        __syncthreads();
    }
#pragma unroll
    for (int i = 0; i < TM; i++) {
        int row = bm + ty * TM + i;
#pragma unroll
        for (int j = 0; j < TNt; j++) {
            int col = bn + tx * TNt + j;
            float v = acc[i][j];
            if (bias)   v += bias[col];
            if (addsrc) v += addsrc[(size_t)row * ldadd + col];
            C[(size_t)row * ldc + col] = v;
        }
    }
}

// ---------------- h0 copy ----------------
__global__ void copyh0_k(const float* __restrict__ h0) {
    int i = blockIdx.x * blockDim.x + threadIdx.x;
    if (i < NH) g_h[i] = h0[i];
}

// ---------------- gather(z one-hot @ Wih_z^T) + GRU gates, one step ----------
// block = n (256 blocks x 256 threads); writes g_h[t]
__global__ void gru_k(int t) {
    int n = blockIdx.x, tid = threadIdx.x;
    __shared__ int sidx[32];
    if (tid < 32) sidx[tid] = g_zidx[((size_t)(t - 1) * NB + n) * 32 + tid];
    __syncthreads();

    float acc[12];
    const float* ai = g_ai + ((size_t)(t - 1) * NB + n) * G3;
#pragma unroll
    for (int c = 0; c < 12; c++) acc[c] = ai[tid + 256 * c];

    for (int s = 0; s < 32; s++) {
        const float* row = g_WihT + (size_t)(s * 32 + sidx[s]) * G3;
#pragma unroll
        for (int c = 0; c < 12; c++) acc[c] += row[tid + 256 * c];
    }

    const float* gh = g_gh + (size_t)n * G3;
    const float* hp = g_h + ((size_t)(t - 1) * NB + n) * HD;
    float*       ho = g_h + ((size_t)t * NB + n) * HD;
#pragma unroll
    for (int c = 0; c < 4; c++) {
        int j = tid + 256 * c;
        float ir = acc[c], iu = acc[c + 4], inn = acc[c + 8];
        float hr = gh[j], hu = gh[HD + j], hn = gh[2 * HD + j];
        float r = 1.0f / (1.0f + expf(-(ir + hr)));
        float u = 1.0f / (1.0f + expf(-(iu + hu)));
        float nn = tanhf(inn + r * hn);
        ho[j] = (1.0f - u) * nn + u * hp[j];
    }
}

// ---------------- categorical sample: argmax(zl + gumbel), first-max wins ----
// grid = 256 (n), block = 1024 (warp per s, lane per c)
__global__ void sample_k(int t, const float* __restrict__ zl) {
    int n = blockIdx.x;
    int s = threadIdx.x >> 5, c = threadIdx.x & 31;
    size_t off = (size_t)n * ZDIM + s * 32 + c;
    float v = zl[off] + g_gum[(size_t)t * NZ + off];
    float m = v;
#pragma unroll
    for (int o = 16; o > 0; o >>= 1) m = fmaxf(m, __shfl_xor_sync(0xffffffffu, m, o));
    unsigned b = __ballot_sync(0xffffffffu, v == m);
    if (c == 0) g_zidx[((size_t)t * NB + n) * 32 + s] = __ffs(b) - 1;
}

// ---------------- decoder z one-hot gather: out_x += sum_s dec_W[H+s*32+idx] -
__global__ void decz_k(const float* __restrict__ decW, float* __restrict__ outx) {
    int tn = blockIdx.x, tid = threadIdx.x;
    __shared__ int sidx[32];
    if (tid < 32) sidx[tid] = g_zidx[(size_t)tn * 32 + tid];
    __syncthreads();
    float* o = outx + (size_t)tn * ZDIM;
    float acc[4];
#pragma unroll
    for (int c = 0; c < 4; c++) acc[c] = o[tid + 256 * c];
    for (int s = 0; s < 32; s++) {
        const float* row = decW + (size_t)(HD + s * 32 + sidx[s]) * ZDIM;
#pragma unroll
        for (int c = 0; c < 4; c++) acc[c] += row[tid + 256 * c];
    }
#pragma unroll
    for (int c = 0; c < 4; c++) o[tid + 256 * c] = acc[c];
}

// ---------------- reward / continue heads ----------------
__global__ void rc_k(const float* __restrict__ rw, const float* __restrict__ cw,
                     const float* __restrict__ cb, float* __restrict__ out) {
    int tn = blockIdx.x, tid = threadIdx.x;
    const float* h = g_h + (size_t)tn * HD;
    float sr = 0.0f, sc = 0.0f;
    for (int j = tid; j < HD; j += 128) {
        float hv = h[j];
        sr += hv * rw[j];
        sc += hv * cw[j];
    }
    __shared__ float br[128], bc[128];
    br[tid] = sr; bc[tid] = sc;
    __syncthreads();
    for (int o = 64; o > 0; o >>= 1) {
        if (tid < o) { br[tid] += br[tid + o]; bc[tid] += bc[tid + o]; }
        __syncthreads();
    }
    if (tid == 0) {
        out[OFF_R + tn] = br[0];
        out[OFF_C + tn] = bc[0] + cb[0];
    }
}

// ---------------- launch ----------------
extern "C" void kernel_launch(void* const* d_in, const int* in_sizes, int n_in,
                              void* d_out, int out_size) {
    const float* x    = (const float*)d_in[0];
    const float* a    = (const float*)d_in[1];
    const float* h0   = (const float*)d_in[2];
    const float* encW = (const float*)d_in[3];
    const float* encb = (const float*)d_in[4];
    const float* Wih  = (const float*)d_in[5];
    const float* Whh  = (const float*)d_in[6];
    const float* bih  = (const float*)d_in[7];
    const float* bhh  = (const float*)d_in[8];
    const float* decW = (const float*)d_in[9];
    const float* decb = (const float*)d_in[10];
    const float* dynW = (const float*)d_in[11];
    const float* dynb = (const float*)d_in[12];
    const float* rewW = (const float*)d_in[13];
    const float* conW = (const float*)d_in[14];
    const float* conb = (const float*)d_in[15];
    float* out = (float*)d_out;

    float *p_ee, *p_ai, *p_h, *p_gh, *p_WhhT, *p_WihT;
    cudaGetSymbolAddress((void**)&p_ee,   g_ee);
    cudaGetSymbolAddress((void**)&p_ai,   g_ai);
    cudaGetSymbolAddress((void**)&p_h,    g_h);
    cudaGetSymbolAddress((void**)&p_gh,   g_gh);
    cudaGetSymbolAddress((void**)&p_WhhT, g_WhhT);
    cudaGetSymbolAddress((void**)&p_WihT, g_WihT);

    // --- parallel precompute ---
    keys_k<<<1, 64>>>();
    gumbel_k<<<(int)(((size_t)TNP * ZDIM + 255) / 256), 256>>>();
    transpose_k<<<dim3(32, 96), dim3(32, 8)>>>(Whh, p_WhhT, G3, HD);     // Whh [3072,1024] -> [1024,3072]
    transpose_k<<<dim3(34, 96), dim3(32, 8)>>>(Wih, p_WihT, G3, KAW);    // Wih [3072,1072] -> [1072,3072]
    // ee = e @ enc_W[H:] + enc_b   [16384,1024]x[1024,1024]
    sgemm_k<128,128,8,8,8><<<dim3(ZDIM/128, TNP/128), 256>>>(
        x, ZDIM, encW + (size_t)HD * ZDIM, ZDIM, p_ee, ZDIM, ZDIM, encb, nullptr, 0);
    // ai = a @ Wih_a^T + bih   [16384,48]x[48,3072]
    sgemm_k<128,128,8,8,8><<<dim3(G3/128, TNP/128), 256>>>(
        a, AD, p_WihT + (size_t)ZDIM * G3, G3, p_ai, G3, AD, bih, nullptr, 0);

    // --- t = 0 ---
    cudaMemcpyAsync(p_h, h0, (size_t)NH * sizeof(float), cudaMemcpyDeviceToDevice, 0);
    sgemm_k<64,64,8,4,4><<<dim3(ZDIM/64, NB/64), 256>>>(
        p_h, HD, encW, ZDIM, out + OFF_PRIOR, ZDIM, HD, nullptr, p_ee, ZDIM);
    sample_k<<<NB, 1024>>>(0, out + OFF_PRIOR);

    // --- sequential steps ---
    for (int t = 1; t < TT; t++) {
        sgemm_k<64,64,8,4,4><<<dim3(G3/64, NB/64), 256>>>(
            p_h + (size_t)(t - 1) * NH, HD, p_WhhT, G3, p_gh, G3, HD, bhh, nullptr, 0);
        gru_k<<<NB, 256>>>(t);
        sgemm_k<64,64,8,4,4><<<dim3(ZDIM/64, NB/64), 256>>>(
            p_h + (size_t)t * NH, HD, encW, ZDIM, out + OFF_PRIOR + (size_t)t * NZ, ZDIM,
            HD, nullptr, p_ee + (size_t)t * NZ, ZDIM);
        sample_k<<<NB, 1024>>>(t, out + OFF_PRIOR + (size_t)t * NZ);
    }

    // --- parallel heads ---
    sgemm_k<128,128,8,8,8><<<dim3(ZDIM/128, TNP/128), 256>>>(
        p_h, HD, decW, ZDIM, out + OFF_X, ZDIM, HD, decb, nullptr, 0);
    decz_k<<<TNP, 256>>>(decW, out + OFF_X);
    sgemm_k<128,128,8,8,8><<<dim3(ZDIM/128, TNP/128), 256>>>(
        p_h, HD, dynW, ZDIM, out + OFF_POST, ZDIM, HD, dynb, nullptr, 0);
    rc_k<<<TNP, 128>>>(rewW, conW, conb, out);
}

// round 6
// speedup vs baseline: 1.3923x; 1.3923x over previous
#include <cuda_runtime.h>
#include <stdint.h>
#include <math.h>

// ---------------- problem constants ----------------
#define TT   64            // T
#define NB   256           // N
#define HD   1024          // H
#define ZDIM 1024          // ZS*ZC
#define AD   48            // AS*AC
#define G3   3072          // 3H
#define KAW  1072          // ZDIM + AD
#define NCAT 4096          // G3 + ZDIM (fused step-GEMM width)
#define TNP  (TT*NB)       // 16384
#define NZ   (NB*ZDIM)     // 262144
#define NH   (NB*HD)       // 262144

// output layout (floats): x_logits, r_loc, c_logits, z_prior_logits, z_post_logits
#define OFF_X     ((size_t)0)
#define OFF_R     ((size_t)TT*NB*ZDIM)
#define OFF_C     (OFF_R + (size_t)TT*NB)
#define OFF_PRIOR (OFF_C + (size_t)TT*NB)
#define OFF_POST  (OFF_PRIOR + (size_t)TT*NB*ZDIM)

// ---------------- device scratch (static, no allocs) ----------------
__device__ float g_ee  [(size_t)TNP*ZDIM];  // e@enc_W[H:] + enc_b
__device__ float g_gum [(size_t)TNP*ZDIM];  // gumbel noise
__device__ float g_ai  [(size_t)TNP*G3];    // a@Wih_a^T + bih
__device__ float g_h   [(size_t)TNP*HD];    // all hidden states
__device__ float g_gh  [NB*G3];             // h@Whh^T + bhh (one step)
__device__ float g_Wcat[(size_t)HD*NCAT];   // [Whh^T | enc_W[:H]]  [k][0:3072|3072:4096]
__device__ float g_WihT[(size_t)KAW*G3];    // Wih^T  [k][g]
__device__ int   g_zidx[TT*NB*32];          // sampled categorical indices
__device__ unsigned g_keys[2*TT];           // per-timestep threefry keys

// ---------------- threefry2x32-20 (JAX-compatible) ----------------
__device__ __forceinline__ void tf2x32(unsigned k0, unsigned k1,
                                       unsigned x0, unsigned x1,
                                       unsigned &o0, unsigned &o1) {
    unsigned ks0 = k0, ks1 = k1, ks2 = k0 ^ k1 ^ 0x1BD11BDAu;
    x0 += ks0; x1 += ks1;
    const int RA[4] = {13, 15, 26, 6};
    const int RB[4] = {17, 29, 16, 24};
#pragma unroll
    for (int i = 0; i < 5; i++) {
#pragma unroll
        for (int j = 0; j < 4; j++) {
            int r = (i & 1) ? RB[j] : RA[j];
            x0 += x1;
            x1 = (x1 << r) | (x1 >> (32 - r));
            x1 ^= x0;
        }
        unsigned a = (i == 0) ? ks1 : (i == 1) ? ks2 : (i == 2) ? ks0 : (i == 3) ? ks1 : ks2;
        unsigned b = (i == 0) ? ks2 : (i == 1) ? ks0 : (i == 2) ? ks1 : (i == 3) ? ks2 : ks0;
        x0 += a; x1 += b + (unsigned)(i + 1);
    }
    o0 = x0; o1 = x1;
}

__global__ void keys_k() {
    int t = threadIdx.x;
    if (t < TT) {
        unsigned o0, o1;
        tf2x32(0u, 42u, 0u, (unsigned)t, o0, o1);
        g_keys[2*t]   = o0;
        g_keys[2*t+1] = o1;
    }
}

__global__ void gumbel_k() {
    size_t L = (size_t)blockIdx.x * blockDim.x + threadIdx.x;
    if (L >= (size_t)TNP * ZDIM) return;
    int t = (int)(L >> 18);            // NZ = 2^18
    unsigned i = (unsigned)(L & 0x3FFFFu);
    unsigned o0, o1;
    tf2x32(g_keys[2*t], g_keys[2*t+1], 0u, i, o0, o1);
    unsigned bits = o0 ^ o1;
    float u = __uint_as_float((bits >> 9) | 0x3f800000u) - 1.0f;
    if (!(u > 0.0f)) u = 1.17549435e-38f;
    float l1 = (float)log((double)u);
    float g  = -(float)log((double)(-l1));
    g_gum[L] = g;
}

// ---------------- transpose: out[c*ldout + r] = in[r*C + c] ----------------
__global__ void transpose_k(const float* __restrict__ in, float* __restrict__ outp,
                            int R, int C, int ldout) {
    __shared__ float tile[32][33];
    int c0 = blockIdx.x * 32, r0 = blockIdx.y * 32;
    int x = threadIdx.x, y = threadIdx.y;
#pragma unroll
    for (int dy = 0; dy < 32; dy += 8) {
        int r = r0 + y + dy, c = c0 + x;
        if (r < R && c < C) tile[y + dy][x] = in[(size_t)r * C + c];
    }
    __syncthreads();
#pragma unroll
    for (int dy = 0; dy < 32; dy += 8) {
        int oc = c0 + y + dy, orr = r0 + x;   // oc = col of in, orr = row of in
        if (oc < C && orr < R) outp[(size_t)oc * ldout + orr] = tile[x][y + dy];
    }
}

// copy enc_W[:H] into Wcat columns 3072..4095
__global__ void enccopy_k(const float* __restrict__ encW) {
    int idx = blockIdx.x * blockDim.x + threadIdx.x;   // 1024*1024
    int k = idx >> 10, c = idx & 1023;
    g_Wcat[(size_t)k * NCAT + G3 + c] = encW[(size_t)k * ZDIM + c];
}

// ---------------- generic SGEMM (proven core): C = A@B (+bias)(+addsrc) ----
// single-buffer, scalar smem fill (coalesced global), As padded (+1) to kill
// STS bank conflicts. Accumulation order over k is monotonic (bit-stable).
template<int BM, int BN, int BK, int TM, int TNt>
__global__ void sgemm_k(const float* __restrict__ A, int lda,
                        const float* __restrict__ B, int ldb,
                        float* __restrict__ C, int ldc, int K,
                        const float* __restrict__ bias,
                        const float* __restrict__ addsrc, int ldadd) {
    constexpr int TH = (BM / TM) * (BN / TNt);
    __shared__ float As[BK][BM + 1];
    __shared__ float Bs[BK][BN];
    int tid = threadIdx.x;
    int bm = blockIdx.y * BM, bn = blockIdx.x * BN;
    int tx = tid % (BN / TNt), ty = tid / (BN / TNt);
    float acc[TM][TNt];
#pragma unroll
    for (int i = 0; i < TM; i++)
#pragma unroll
        for (int j = 0; j < TNt; j++) acc[i][j] = 0.0f;

    for (int k0 = 0; k0 < K; k0 += BK) {
#pragma unroll
        for (int i = tid; i < BM * BK; i += TH) {
            int r = i / BK, c = i % BK;
            As[c][r] = A[(size_t)(bm + r) * lda + k0 + c];
        }
#pragma unroll
        for (int i = tid; i < BK * BN; i += TH) {
            int r = i / BN, c = i % BN;
            Bs[r][c] = B[(size_t)(k0 + r) * ldb + bn + c];
        }
        __syncthreads();
#pragma unroll
        for (int kk = 0; kk < BK; kk++) {
            float av[TM], bv[TNt];
#pragma unroll
            for (int i = 0; i < TM; i++) av[i] = As[kk][ty * TM + i];
#pragma unroll
            for (int j = 0; j < TNt; j++) bv[j] = Bs[kk][tx * TNt + j];
#pragma unroll
            for (int i = 0; i < TM; i++)
#pragma unroll
                for (int j = 0; j < TNt; j++)
                    acc[i][j] = fmaf(av[i], bv[j], acc[i][j]);
        }
        __syncthreads();
    }
#pragma unroll
    for (int i = 0; i < TM; i++) {
        int row = bm + ty * TM + i;
#pragma unroll
        for (int j = 0; j < TNt; j++) {
            int col = bn + tx * TNt + j;
            float v = acc[i][j];
            if (bias)   v += bias[col];
            if (addsrc) v += addsrc[(size_t)row * ldadd + col];
            C[(size_t)row * ldc + col] = v;
        }
    }
}

// ---------------- fused step GEMM: h_t @ [Whh^T | encW] --------------------
// Same proven core (BM=64,BN=64,BK=16,TM=4,TN=4,256 thr), split epilogue:
// global cols 0..3071 -> g_gh (+bhh); cols 3072..4095 -> prior (+ee_t).
__global__ void catgemm_k(const float* __restrict__ h,     // [256,1024]
                          const float* __restrict__ bhh,
                          const float* __restrict__ ee_t,  // [256,1024]
                          float* __restrict__ prior)       // [256,1024]
{
    constexpr int BM = 64, BN = 64, BK = 16, TM = 4, TN = 4;
    constexpr int TH = (BM / TM) * (BN / TN);  // 256
    __shared__ float As[BK][BM + 1];
    __shared__ float Bs[BK][BN];
    int tid = threadIdx.x;
    int bm = blockIdx.y * BM, bn = blockIdx.x * BN;
    int tx = tid % (BN / TN), ty = tid / (BN / TN);
    float acc[TM][TN];
#pragma unroll
    for (int i = 0; i < TM; i++)
#pragma unroll
        for (int j = 0; j < TN; j++) acc[i][j] = 0.0f;

    for (int k0 = 0; k0 < HD; k0 += BK) {
#pragma unroll
        for (int i = tid; i < BM * BK; i += TH) {
            int r = i / BK, c = i % BK;
            As[c][r] = h[(size_t)(bm + r) * HD + k0 + c];
        }
#pragma unroll
        for (int i = tid; i < BK * BN; i += TH) {
            int r = i / BN, c = i % BN;
            Bs[r][c] = g_Wcat[(size_t)(k0 + r) * NCAT + bn + c];
        }
        __syncthreads();
#pragma unroll
        for (int kk = 0; kk < BK; kk++) {
            float av[TM], bv[TN];
#pragma unroll
            for (int i = 0; i < TM; i++) av[i] = As[kk][ty * TM + i];
#pragma unroll
            for (int j = 0; j < TN; j++) bv[j] = Bs[kk][tx * TN + j];
#pragma unroll
            for (int i = 0; i < TM; i++)
#pragma unroll
                for (int j = 0; j < TN; j++)
                    acc[i][j] = fmaf(av[i], bv[j], acc[i][j]);
        }
        __syncthreads();
    }

    bool is_gh = (bn < G3);   // BN=64 divides G3 -> uniform per block
#pragma unroll
    for (int i = 0; i < TM; i++) {
        int row = bm + ty * TM + i;
#pragma unroll
        for (int j = 0; j < TN; j++) {
            int col = bn + tx * TN + j;
            float v = acc[i][j];
            if (is_gh) {
                g_gh[(size_t)row * G3 + col] = v + bhh[col];
            } else {
                int c0 = col - G3;
                prior[(size_t)row * ZDIM + c0] = v + ee_t[(size_t)row * ZDIM + c0];
            }
        }
    }
}

// ---------------- gather(z one-hot @ Wih_z^T) + GRU gates, one step --------
// (proven scalar version) block = n (256 blocks x 256 threads); writes g_h[t]
__global__ void gru_k(int t) {
    int n = blockIdx.x, tid = threadIdx.x;
    __shared__ int sidx[32];
    if (tid < 32) sidx[tid] = g_zidx[((size_t)(t - 1) * NB + n) * 32 + tid];
    __syncthreads();

    float acc[12];
    const float* ai = g_ai + ((size_t)(t - 1) * NB + n) * G3;
#pragma unroll
    for (int c = 0; c < 12; c++) acc[c] = ai[tid + 256 * c];

    for (int s = 0; s < 32; s++) {
        const float* row = g_WihT + (size_t)(s * 32 + sidx[s]) * G3;
#pragma unroll
        for (int c = 0; c < 12; c++) acc[c] += row[tid + 256 * c];
    }

    const float* gh = g_gh + (size_t)n * G3;
    const float* hp = g_h + ((size_t)(t - 1) * NB + n) * HD;
    float*       ho = g_h + ((size_t)t * NB + n) * HD;
#pragma unroll
    for (int c = 0; c < 4; c++) {
        int j = tid + 256 * c;
        float ir = acc[c], iu = acc[c + 4], inn = acc[c + 8];
        float hr = gh[j], hu = gh[HD + j], hn = gh[2 * HD + j];
        float r = 1.0f / (1.0f + expf(-(ir + hr)));
        float u = 1.0f / (1.0f + expf(-(iu + hu)));
        float nn = tanhf(inn + r * hn);
        ho[j] = (1.0f - u) * nn + u * hp[j];
    }
}

// ---------------- categorical sample: argmax(zl + gumbel), first-max wins --
__global__ void sample_k(int t, const float* __restrict__ zl) {
    int n = blockIdx.x;
    int s = threadIdx.x >> 5, c = threadIdx.x & 31;
    size_t off = (size_t)n * ZDIM + s * 32 + c;
    float v = zl[off] + g_gum[(size_t)t * NZ + off];
    float m = v;
#pragma unroll
    for (int o = 16; o > 0; o >>= 1) m = fmaxf(m, __shfl_xor_sync(0xffffffffu, m, o));
    unsigned b = __ballot_sync(0xffffffffu, v == m);
    if (c == 0) g_zidx[((size_t)t * NB + n) * 32 + s] = __ffs(b) - 1;
}

// ---------------- decoder z one-hot gather (proven scalar version) ---------
__global__ void decz_k(const float* __restrict__ decW, float* __restrict__ outx) {
    int tn = blockIdx.x, tid = threadIdx.x;
    __shared__ int sidx[32];
    if (tid < 32) sidx[tid] = g_zidx[(size_t)tn * 32 + tid];
    __syncthreads();
    float* o = outx + (size_t)tn * ZDIM;
    float acc[4];
#pragma unroll
    for (int c = 0; c < 4; c++) acc[c] = o[tid + 256 * c];
    for (int s = 0; s < 32; s++) {
        const float* row = decW + (size_t)(HD + s * 32 + sidx[s]) * ZDIM;
#pragma unroll
        for (int c = 0; c < 4; c++) acc[c] += row[tid + 256 * c];
    }
#pragma unroll
    for (int c = 0; c < 4; c++) o[tid + 256 * c] = acc[c];
}

// ---------------- reward / continue heads ----------------------------------
__global__ void rc_k(const float* __restrict__ rw, const float* __restrict__ cw,
                     const float* __restrict__ cb, float* __restrict__ out) {
    int tn = blockIdx.x, tid = threadIdx.x;
    const float* h = g_h + (size_t)tn * HD;
    float sr = 0.0f, sc = 0.0f;
    for (int j = tid; j < HD; j += 128) {
        float hv = h[j];
        sr += hv * rw[j];
        sc += hv * cw[j];
    }
    __shared__ float br[128], bc[128];
    br[tid] = sr; bc[tid] = sc;
    __syncthreads();
    for (int o = 64; o > 0; o >>= 1) {
        if (tid < o) { br[tid] += br[tid + o]; bc[tid] += bc[tid + o]; }
        __syncthreads();
    }
    if (tid == 0) {
        out[OFF_R + tn] = br[0];
        out[OFF_C + tn] = bc[0] + cb[0];
    }
}

// ---------------- launch ----------------------------------------------------
extern "C" void kernel_launch(void* const* d_in, const int* in_sizes, int n_in,
                              void* d_out, int out_size) {
    const float* x    = (const float*)d_in[0];
    const float* a    = (const float*)d_in[1];
    const float* h0   = (const float*)d_in[2];
    const float* encW = (const float*)d_in[3];
    const float* encb = (const float*)d_in[4];
    const float* Wih  = (const float*)d_in[5];
    const float* Whh  = (const float*)d_in[6];
    const float* bih  = (const float*)d_in[7];
    const float* bhh  = (const float*)d_in[8];
    const float* decW = (const float*)d_in[9];
    const float* decb = (const float*)d_in[10];
    const float* dynW = (const float*)d_in[11];
    const float* dynb = (const float*)d_in[12];
    const float* rewW = (const float*)d_in[13];
    const float* conW = (const float*)d_in[14];
    const float* conb = (const float*)d_in[15];
    float* out = (float*)d_out;

    float *p_ee, *p_ai, *p_h, *p_Wcat, *p_WihT;
    cudaGetSymbolAddress((void**)&p_ee,   g_ee);
    cudaGetSymbolAddress((void**)&p_ai,   g_ai);
    cudaGetSymbolAddress((void**)&p_h,    g_h);
    cudaGetSymbolAddress((void**)&p_Wcat, g_Wcat);
    cudaGetSymbolAddress((void**)&p_WihT, g_WihT);

    // --- parallel precompute ---
    keys_k<<<1, 64>>>();
    gumbel_k<<<(int)(((size_t)TNP * ZDIM + 255) / 256), 256>>>();
    transpose_k<<<dim3(32, 96), dim3(32, 8)>>>(Whh, p_Wcat, G3, HD, NCAT);  // Whh^T -> Wcat[:,0:3072]
    enccopy_k<<<4096, 256>>>(encW);                                          // encW  -> Wcat[:,3072:4096]
    transpose_k<<<dim3(34, 96), dim3(32, 8)>>>(Wih, p_WihT, G3, KAW, G3);    // Wih^T
    // ee = e @ enc_W[H:] + enc_b   [16384,1024]x[1024,1024]
    sgemm_k<128,128,16,8,8><<<dim3(ZDIM / 128, TNP / 128), 256>>>(
        x, ZDIM, encW + (size_t)HD * ZDIM, ZDIM, p_ee, ZDIM, ZDIM, encb, nullptr, 0);
    // ai = a @ Wih_a^T + bih   [16384,48]x[48,3072]
    sgemm_k<128,128,16,8,8><<<dim3(G3 / 128, TNP / 128), 256>>>(
        a, AD, p_WihT + (size_t)ZDIM * G3, G3, p_ai, G3, AD, bih, nullptr, 0);

    // --- sequential rollout (fused gh+prior GEMM per step) ---
    cudaMemcpyAsync(p_h, h0, (size_t)NH * sizeof(float), cudaMemcpyDeviceToDevice, 0);
    for (int t = 0; t < TT; t++) {
        catgemm_k<<<dim3(NCAT / 64, NB / 64), 256>>>(
            p_h + (size_t)t * NH, bhh, p_ee + (size_t)t * NZ,
            out + OFF_PRIOR + (size_t)t * NZ);
        sample_k<<<NB, 1024>>>(t, out + OFF_PRIOR + (size_t)t * NZ);
        if (t < TT - 1) gru_k<<<NB, 256>>>(t + 1);
    }

    // --- parallel heads ---
    sgemm_k<128,128,16,8,8><<<dim3(ZDIM / 128, TNP / 128), 256>>>(
        p_h, HD, decW, ZDIM, out + OFF_X, ZDIM, HD, decb, nullptr, 0);
    decz_k<<<TNP, 256>>>(decW, out + OFF_X);
    sgemm_k<128,128,16,8,8><<<dim3(ZDIM / 128, TNP / 128), 256>>>(
        p_h, HD, dynW, ZDIM, out + OFF_POST, ZDIM, HD, dynb, nullptr, 0);
    rc_k<<<TNP, 128>>>(rewW, conW, conb, out);
}